// round 1
// baseline (speedup 1.0000x reference)
#include <cuda_runtime.h>
#include <cuda_bf16.h>

#define SS 7
#define CCLS 20
#define NCH 25
#define MAXCELLS 8192
#define LAMBDA_COORD 5.0f
#define LAMBDA_NOOBJ 0.5f
#define EPS_SQRT 1e-6f
#define EPS_IOU 1e-10f

// Scratch (no device allocation allowed; __device__ globals are the sanctioned path)
__device__ double g_acc;
__device__ int    g_cnt;
__device__ float  g_tx1[MAXCELLS];
__device__ float  g_ty1[MAXCELLS];
__device__ float  g_tx2[MAXCELLS];
__device__ float  g_ty2[MAXCELLS];
__device__ float  g_ta [MAXCELLS];
__device__ int    g_idx[MAXCELLS];

__global__ void k_init() {
    g_acc = 0.0;
    g_cnt = 0;
}

// Per-cell elementwise losses + compaction of object-target boxes.
__global__ void k_main(const float* __restrict__ pred,
                       const float* __restrict__ targ,
                       int M) {
    int i = blockIdx.x * blockDim.x + threadIdx.x;
    double local = 0.0;
    if (i < M) {
        const float* pp = pred + (size_t)i * NCH;
        const float* tt = targ + (size_t)i * NCH;
        float t4 = tt[4];
        float p4 = pp[4];
        if (t4 > 0.0f) {
            // coord loss (xy + sqrt-wh), lambda_coord = 5
            float dx = pp[0] - tt[0];
            float dy = pp[1] - tt[1];
            float sw = sqrtf(pp[2] + EPS_SQRT) - sqrtf(tt[2] + EPS_SQRT);
            float sh = sqrtf(pp[3] + EPS_SQRT) - sqrtf(tt[3] + EPS_SQRT);
            local += (double)(LAMBDA_COORD * (dx * dx + dy * dy + sw * sw + sh * sh));
            // class loss
            float cl = 0.0f;
            #pragma unroll
            for (int c = 5; c < NCH; c++) {
                float d = pp[c] - tt[c];
                cl += d * d;
            }
            local += (double)cl;
            // compact this object target's corners + area (order irrelevant: consumer is a max)
            int pos = atomicAdd(&g_cnt, 1);
            float cx = tt[0], cy = tt[1], w = tt[2], h = tt[3];
            float x1 = cx - w * 0.5f, y1 = cy - h * 0.5f;
            float x2 = cx + w * 0.5f, y2 = cy + h * 0.5f;
            g_tx1[pos] = x1;
            g_ty1[pos] = y1;
            g_tx2[pos] = x2;
            g_ty2[pos] = y2;
            g_ta [pos] = (x2 - x1) * (y2 - y1);
            g_idx[pos] = i;
        } else {
            // noobj conf loss: 0.5 * (p_conf - 0)^2
            local += (double)(LAMBDA_NOOBJ * p4 * p4);
        }
    }

    // block reduction (double) -> one atomicAdd per block
    __shared__ double sred[256];
    int tid = threadIdx.x;
    sred[tid] = local;
    __syncthreads();
    for (int s = blockDim.x >> 1; s > 0; s >>= 1) {
        if (tid < s) sred[tid] += sred[tid + s];
        __syncthreads();
    }
    if (tid == 0) atomicAdd(&g_acc, sred[0]);
}

// Single block: conf loss over object cells (max-IoU vs all K object targets),
// then final combine + write out.
__global__ void k_conf_final(const float* __restrict__ pred,
                             float* __restrict__ out,
                             float invB) {
    int K = g_cnt;
    double local = 0.0;
    for (int i = threadIdx.x; i < K; i += blockDim.x) {
        int cell = g_idx[i];
        const float* pp = pred + (size_t)cell * NCH;
        float cx = pp[0], cy = pp[1], w = pp[2], h = pp[3];
        float pc = pp[4];
        float px1 = cx - w * 0.5f, py1 = cy - h * 0.5f;
        float px2 = cx + w * 0.5f, py2 = cy + h * 0.5f;
        float pa  = (px2 - px1) * (py2 - py1);
        float best = -1.0f;
        for (int j = 0; j < K; j++) {
            float iw = fminf(px2, g_tx2[j]) - fmaxf(px1, g_tx1[j]);
            float ih = fminf(py2, g_ty2[j]) - fmaxf(py1, g_ty1[j]);
            iw = fmaxf(iw, 0.0f);
            ih = fmaxf(ih, 0.0f);
            float inter = iw * ih;
            float iou = inter / (pa + g_ta[j] - inter + EPS_IOU);
            best = fmaxf(best, iou);
        }
        float d = pc - best;
        local += (double)(d * d);
    }

    __shared__ double sred[256];
    int tid = threadIdx.x;
    sred[tid] = local;
    __syncthreads();
    for (int s = blockDim.x >> 1; s > 0; s >>= 1) {
        if (tid < s) sred[tid] += sred[tid + s];
        __syncthreads();
    }
    if (tid == 0) {
        out[0] = (float)((g_acc + sred[0]) * (double)invB);
    }
}

extern "C" void kernel_launch(void* const* d_in, const int* in_sizes, int n_in,
                              void* d_out, int out_size) {
    const float* pred = (const float*)d_in[0];
    const float* targ = (const float*)d_in[1];
    float* out = (float*)d_out;

    int total = in_sizes[0];           // B * S * S * N
    int M = total / NCH;               // number of cells
    int B = M / (SS * SS);
    float invB = 1.0f / (float)B;

    k_init<<<1, 1>>>();
    int threads = 256;
    int blocks = (M + threads - 1) / threads;
    k_main<<<blocks, threads>>>(pred, targ, M);
    k_conf_final<<<1, 256>>>(pred, out, invB);
}

// round 2
// speedup vs baseline: 3.8936x; 3.8936x over previous
#include <cuda_runtime.h>
#include <cuda_bf16.h>

#define SS 7
#define NCH 25
#define MAXCELLS 8192
#define SH_CAP 1024
#define LAMBDA_COORD 5.0f
#define LAMBDA_NOOBJ 0.5f
#define EPS_SQRT 1e-6f
#define EPS_IOU 1e-10f
#define TPB 128

// Scratch (__device__ globals; statics zero-initialized -> first call correct,
// kernel self-resets counters at the end -> every graph replay identical)
__device__ double g_part[128];
__device__ int    g_cnt  = 0;   // compacted object-cell count
__device__ int    g_done = 0;   // block arrival counter
__device__ float  g_tx1[MAXCELLS];
__device__ float  g_ty1[MAXCELLS];
__device__ float  g_tx2[MAXCELLS];
__device__ float  g_ty2[MAXCELLS];
__device__ float  g_ta [MAXCELLS];
__device__ int    g_idx[MAXCELLS];

__global__ void __launch_bounds__(TPB)
k_yolo_fused(const float* __restrict__ pred,
             const float* __restrict__ targ,
             float* __restrict__ out,
             int M, int nblocks, float invB) {
    int tid = threadIdx.x;
    int i = blockIdx.x * TPB + tid;

    // ---------------- Phase 1: per-cell losses + target compaction ----------
    double local = 0.0;
    if (i < M) {
        const float* pp = pred + (size_t)i * NCH;
        const float* tt = targ + (size_t)i * NCH;
        float t4 = tt[4];
        float p4 = pp[4];
        if (t4 > 0.0f) {
            // coord loss: xy MSE + sqrt-wh MSE, lambda = 5
            float dx = pp[0] - tt[0];
            float dy = pp[1] - tt[1];
            float sw = sqrtf(pp[2] + EPS_SQRT) - sqrtf(tt[2] + EPS_SQRT);
            float sh = sqrtf(pp[3] + EPS_SQRT) - sqrtf(tt[3] + EPS_SQRT);
            float cl = 0.0f;
            #pragma unroll
            for (int c = 5; c < NCH; c++) {
                float d = pp[c] - tt[c];
                cl += d * d;
            }
            local += (double)(LAMBDA_COORD * (dx * dx + dy * dy + sw * sw + sh * sh) + cl);
            // compact object-target corners/area (order irrelevant: consumer is a max)
            int pos = atomicAdd(&g_cnt, 1);
            float cx = tt[0], cy = tt[1], w = tt[2], h = tt[3];
            float x1 = cx - w * 0.5f, y1 = cy - h * 0.5f;
            float x2 = cx + w * 0.5f, y2 = cy + h * 0.5f;
            g_tx1[pos] = x1;
            g_ty1[pos] = y1;
            g_tx2[pos] = x2;
            g_ty2[pos] = y2;
            g_ta [pos] = (x2 - x1) * (y2 - y1);
            g_idx[pos] = i;
        } else {
            local += (double)(LAMBDA_NOOBJ * p4 * p4);
        }
    }

    // block reduction (double)
    __shared__ double sred[TPB];
    sred[tid] = local;
    __syncthreads();
    for (int s = TPB >> 1; s > 0; s >>= 1) {
        if (tid < s) sred[tid] += sred[tid + s];
        __syncthreads();
    }
    if (tid == 0) g_part[blockIdx.x] = sred[0];

    // ---------------- arrive; last block does phase 2 -----------------------
    __threadfence();
    __shared__ int is_last;
    if (tid == 0) is_last = (atomicAdd(&g_done, 1) == nblocks - 1) ? 1 : 0;
    __syncthreads();
    if (!is_last) return;

    // ---------------- Phase 2 (single block): conf loss + finalize ----------
    int K = g_cnt;

    // stage target boxes into shared memory
    __shared__ float s_tx1[SH_CAP], s_ty1[SH_CAP], s_tx2[SH_CAP], s_ty2[SH_CAP], s_ta[SH_CAP];
    int Ksh = K < SH_CAP ? K : SH_CAP;
    for (int j = tid; j < Ksh; j += TPB) {
        s_tx1[j] = g_tx1[j];
        s_ty1[j] = g_ty1[j];
        s_tx2[j] = g_tx2[j];
        s_ty2[j] = g_ty2[j];
        s_ta [j] = g_ta [j];
    }
    __syncthreads();

    double l2 = 0.0;
    for (int ii = tid; ii < K; ii += TPB) {
        int cell = g_idx[ii];
        const float* pp = pred + (size_t)cell * NCH;
        float cx = pp[0], cy = pp[1], w = pp[2], h = pp[3];
        float pc = pp[4];
        float px1 = cx - w * 0.5f, py1 = cy - h * 0.5f;
        float px2 = cx + w * 0.5f, py2 = cy + h * 0.5f;
        float pa  = (px2 - px1) * (py2 - py1);
        float best = -1.0f;
        for (int j = 0; j < Ksh; j++) {
            float iw = fminf(px2, s_tx2[j]) - fmaxf(px1, s_tx1[j]);
            float ih = fminf(py2, s_ty2[j]) - fmaxf(py1, s_ty1[j]);
            iw = fmaxf(iw, 0.0f);
            ih = fmaxf(ih, 0.0f);
            float inter = iw * ih;
            float iou = __fdividef(inter, pa + s_ta[j] - inter + EPS_IOU);
            best = fmaxf(best, iou);
        }
        for (int j = Ksh; j < K; j++) {   // overflow path (K > SH_CAP), normally empty
            float iw = fminf(px2, g_tx2[j]) - fmaxf(px1, g_tx1[j]);
            float ih = fminf(py2, g_ty2[j]) - fmaxf(py1, g_ty1[j]);
            iw = fmaxf(iw, 0.0f);
            ih = fmaxf(ih, 0.0f);
            float inter = iw * ih;
            float iou = __fdividef(inter, pa + g_ta[j] - inter + EPS_IOU);
            best = fmaxf(best, iou);
        }
        float d = pc - best;
        l2 += (double)(d * d);
    }

    sred[tid] = l2;
    __syncthreads();
    for (int s = TPB >> 1; s > 0; s >>= 1) {
        if (tid < s) sred[tid] += sred[tid + s];
        __syncthreads();
    }
    if (tid == 0) {
        double tot = sred[0];
        for (int b = 0; b < nblocks; b++) tot += g_part[b];
        out[0] = (float)(tot * (double)invB);
        g_cnt  = 0;   // reset for next graph replay (deterministic state)
        g_done = 0;
    }
}

extern "C" void kernel_launch(void* const* d_in, const int* in_sizes, int n_in,
                              void* d_out, int out_size) {
    const float* pred = (const float*)d_in[0];
    const float* targ = (const float*)d_in[1];
    float* out = (float*)d_out;

    int total = in_sizes[0];           // B * S * S * N
    int M = total / NCH;               // number of cells (6272)
    int B = M / (SS * SS);
    float invB = 1.0f / (float)B;

    int nblocks = (M + TPB - 1) / TPB; // 49
    k_yolo_fused<<<nblocks, TPB>>>(pred, targ, out, M, nblocks, invB);
}

// round 3
// speedup vs baseline: 6.4714x; 1.6620x over previous
#include <cuda_runtime.h>
#include <cuda_bf16.h>

#define SS 7
#define NCH 25
#define SH_CAP 2048
#define LAMBDA_COORD 5.0f
#define LAMBDA_NOOBJ 0.5f
#define EPS_SQRT 1e-6f
#define EPS_IOU 1e-10f
#define TPB 512
#define MAXBLK 64

// __device__ globals (zero-init; kernel self-resets -> identical on every replay)
__device__ double g_part[MAXBLK];
__device__ int    g_done = 0;

__global__ void __launch_bounds__(TPB)
k_yolo_onepass(const float* __restrict__ pred,
               const float* __restrict__ targ,
               float* __restrict__ out,
               int M, int nblocks, float invB) {
    const int tid  = threadIdx.x;
    const int lane = tid & 31;
    const int i    = blockIdx.x * TPB + tid;   // owned cell

    // ------- Build the (block-local) object-target box list from targ -------
    __shared__ float s_tx1[SH_CAP], s_ty1[SH_CAP], s_tx2[SH_CAP], s_ty2[SH_CAP], s_ta[SH_CAP];
    __shared__ int   s_cnt;
    if (tid == 0) s_cnt = 0;
    __syncthreads();

    for (int j = tid; j < M; j += TPB) {
        float c = __ldg(&targ[(size_t)j * NCH + 4]);
        if (c > 0.0f) {
            int pos = atomicAdd(&s_cnt, 1);
            if (pos < SH_CAP) {
                const float* tt = targ + (size_t)j * NCH;
                float cx = tt[0], cy = tt[1], w = tt[2], h = tt[3];
                float x1 = cx - w * 0.5f, y1 = cy - h * 0.5f;
                float x2 = cx + w * 0.5f, y2 = cy + h * 0.5f;
                s_tx1[pos] = x1;  s_ty1[pos] = y1;
                s_tx2[pos] = x2;  s_ty2[pos] = y2;
                s_ta [pos] = (x2 - x1) * (y2 - y1);
            }
        }
    }
    __syncthreads();
    const int K = s_cnt < SH_CAP ? s_cnt : SH_CAP;

    // ------- Per-owned-cell elementwise losses + pred corners ---------------
    double local = 0.0;
    float px1 = 0.f, py1 = 0.f, px2 = 0.f, py2 = 0.f, pa = 0.f, pc = 0.f;
    bool isObj = false;
    if (i < M) {
        const float* pp = pred + (size_t)i * NCH;
        const float* tt = targ + (size_t)i * NCH;
        float t4 = tt[4];
        pc = pp[4];
        if (t4 > 0.0f) {
            isObj = true;
            float dx = pp[0] - tt[0];
            float dy = pp[1] - tt[1];
            float sw = sqrtf(pp[2] + EPS_SQRT) - sqrtf(tt[2] + EPS_SQRT);
            float sh = sqrtf(pp[3] + EPS_SQRT) - sqrtf(tt[3] + EPS_SQRT);
            float cl = 0.0f;
            #pragma unroll
            for (int c = 5; c < NCH; c++) {
                float d = pp[c] - tt[c];
                cl += d * d;
            }
            local += (double)(LAMBDA_COORD * (dx * dx + dy * dy + sw * sw + sh * sh) + cl);
            float cx = pp[0], cy = pp[1], w = pp[2], h = pp[3];
            px1 = cx - w * 0.5f;  py1 = cy - h * 0.5f;
            px2 = cx + w * 0.5f;  py2 = cy + h * 0.5f;
            pa  = (px2 - px1) * (py2 - py1);
        } else {
            local += (double)(LAMBDA_NOOBJ * pc * pc);
        }
    }

    // ------- Warp-cooperative conf loss for object cells --------------------
    unsigned obj_mask = __ballot_sync(0xffffffffu, isObj);
    while (obj_mask) {
        int src = __ffs(obj_mask) - 1;
        obj_mask &= obj_mask - 1;
        float bx1 = __shfl_sync(0xffffffffu, px1, src);
        float by1 = __shfl_sync(0xffffffffu, py1, src);
        float bx2 = __shfl_sync(0xffffffffu, px2, src);
        float by2 = __shfl_sync(0xffffffffu, py2, src);
        float ba  = __shfl_sync(0xffffffffu, pa,  src);
        float best = -1.0f;
        for (int j = lane; j < K; j += 32) {
            float iw = fminf(bx2, s_tx2[j]) - fmaxf(bx1, s_tx1[j]);
            float ih = fminf(by2, s_ty2[j]) - fmaxf(by1, s_ty1[j]);
            iw = fmaxf(iw, 0.0f);
            ih = fmaxf(ih, 0.0f);
            float inter = iw * ih;
            float iou = __fdividef(inter, ba + s_ta[j] - inter + EPS_IOU);
            best = fmaxf(best, iou);
        }
        #pragma unroll
        for (int off = 16; off > 0; off >>= 1)
            best = fmaxf(best, __shfl_xor_sync(0xffffffffu, best, off));
        if (lane == src) {
            float d = pc - best;
            local += (double)(d * d);
        }
    }

    // ------- Block reduction (double) ---------------------------------------
    __shared__ double sred[TPB];
    sred[tid] = local;
    __syncthreads();
    for (int s = TPB >> 1; s > 0; s >>= 1) {
        if (tid < s) sred[tid] += sred[tid + s];
        __syncthreads();
    }
    if (tid == 0) g_part[blockIdx.x] = sred[0];

    // ------- Last block finalizes (tiny) ------------------------------------
    __threadfence();
    __shared__ int is_last;
    if (tid == 0) is_last = (atomicAdd(&g_done, 1) == nblocks - 1) ? 1 : 0;
    __syncthreads();
    if (!is_last) return;

    if (tid == 0) {
        double tot = 0.0;
        for (int b = 0; b < nblocks; b++) tot += g_part[b];
        out[0] = (float)(tot * (double)invB);
        g_done = 0;   // reset for next graph replay
    }
}

extern "C" void kernel_launch(void* const* d_in, const int* in_sizes, int n_in,
                              void* d_out, int out_size) {
    const float* pred = (const float*)d_in[0];
    const float* targ = (const float*)d_in[1];
    float* out = (float*)d_out;

    int total = in_sizes[0];           // B * S * S * N
    int M = total / NCH;               // 6272 cells
    int B = M / (SS * SS);
    float invB = 1.0f / (float)B;

    int nblocks = (M + TPB - 1) / TPB; // 13
    k_yolo_onepass<<<nblocks, TPB>>>(pred, targ, out, M, nblocks, invB);
}